// round 11
// baseline (speedup 1.0000x reference)
#include <cuda_runtime.h>
#include <stdint.h>

// ---------------------------------------------------------------------------
// PGExplainer forward: masked_adj = adj * 0.5*(mask + mask^T)
// out[c,r] = cnt(c,r) * 0.5 * (S(c,r) + S(r,c)),  S = sum of sampled values
// Persistent kernel: phase0 (clear+decode+noise+GEMM) -> grid barrier ->
// phase1 (interleaved 400MB zero + edge MLP/sample/hash-insert). Then k_sym.
// ---------------------------------------------------------------------------

#define N_NODES 10000
#define N_EDGES 640000
#define D_EMB   128
#define HID     64

#define OUT_ELEMS ((size_t)N_NODES * N_NODES)   // 1e8 floats = 400 MB
#define OUT_F4    (OUT_ELEMS / 4)               // 25,000,000 float4

#define HCAP  (1 << 21)
#define HMASK (HCAP - 1)
#define HCAP4 (HCAP / 4)

#define NBLK   296                               // 2 blocks/SM on 148 SMs
#define NTHR   256
#define STRIDE (NBLK * NTHR)                     // 75,776 threads
#define NGRP   (NBLK * 32)                       // 9,472 8-lane edge groups
#define ZITER  330                               // 330*75776 >= 25M
#define GEMM_HALF_TILES 313                      // ceil(10000/32)
#define GEMM_TILES      (2 * GEMM_HALF_TILES)    // 626

// Scratch (device globals).
__device__ float g_A[N_NODES * HID];
__device__ float g_B[N_NODES * HID];
__device__ float g_noise[N_EDGES];
__device__ int2  g_ci[N_EDGES];
__device__ int   g_slot[N_EDGES];
__device__ int   g_keys[HCAP];          // -1 = empty
__device__ float g_sums[HCAP];
__device__ int   g_cnts[HCAP];
// Grid barrier state: counter returns to 0 each use; flag is a monotonically
// increasing epoch (replay-safe, never reset).
__device__ unsigned          g_barcnt;
__device__ volatile unsigned g_barflag;

__device__ __forceinline__ uint32_t cell_hash(int key) {
    return ((uint32_t)key * 0x9E3779B1u) >> (32 - 21);
}

__device__ __forceinline__ uint32_t probe_slot(int key) {
    uint32_t h = cell_hash(key);
    while (true) {
        int k = g_keys[h];
        if (k == key) break;
        if (k == -1) {
            int old = atomicCAS(&g_keys[h], -1, key);
            if (old == -1 || old == key) break;
        }
        h = (h + 1) & HMASK;
    }
    return h;
}

// ---------------------------------------------------------------------------
// threefry2x32 (JAX schedule), key = (0, 42); partitionable stream.
// ---------------------------------------------------------------------------
__device__ __forceinline__ uint32_t rotl32(uint32_t x, int d) {
    return (x << d) | (x >> (32 - d));
}

__device__ __forceinline__ void threefry2x32(uint32_t k0, uint32_t k1,
                                             uint32_t x0, uint32_t x1,
                                             uint32_t& o0, uint32_t& o1) {
    uint32_t ks0 = k0, ks1 = k1, ks2 = k0 ^ k1 ^ 0x1BD11BDAu;
#define TF_R4(a, b, c, d)                            \
    x0 += x1; x1 = rotl32(x1, a); x1 ^= x0;          \
    x0 += x1; x1 = rotl32(x1, b); x1 ^= x0;          \
    x0 += x1; x1 = rotl32(x1, c); x1 ^= x0;          \
    x0 += x1; x1 = rotl32(x1, d); x1 ^= x0;
    x0 += ks0; x1 += ks1;
    TF_R4(13, 15, 26, 6);  x0 += ks1; x1 += ks2 + 1u;
    TF_R4(17, 29, 16, 24); x0 += ks2; x1 += ks0 + 2u;
    TF_R4(13, 15, 26, 6);  x0 += ks0; x1 += ks1 + 3u;
    TF_R4(17, 29, 16, 24); x0 += ks1; x1 += ks2 + 4u;
    TF_R4(13, 15, 26, 6);  x0 += ks2; x1 += ks0 + 5u;
#undef TF_R4
    o0 = x0; o1 = x1;
}

__device__ __forceinline__ float noise_from_bits(uint32_t bits) {
    float u = __uint_as_float((bits >> 9) | 0x3f800000u) - 1.0f;   // [0,1)
    return logf(u) - log1pf(-u);   // u==0 -> -inf -> sigmoid -> 0
}

// ---------------------------------------------------------------------------
// K_main: persistent kernel, NBLK co-resident blocks.
// ---------------------------------------------------------------------------
__global__ void __launch_bounds__(NTHR, 2) k_main(const float* __restrict__ embed,
                                                  const float* __restrict__ W1,
                                                  const void* __restrict__ ei_raw,
                                                  const float* __restrict__ b1,
                                                  const float* __restrict__ W2,
                                                  const float* __restrict__ b2,
                                                  float4* __restrict__ out) {
    __shared__ float    es[32 * D_EMB];      // 16 KB (GEMM staging)
    __shared__ int      s_flag;
    __shared__ unsigned s_target;

    int tid = threadIdx.x, bid = blockIdx.x;

    // Read barrier epoch base BEFORE any arrival (flag cannot advance until
    // every block of this launch arrives, so all blocks read the same base).
    if (tid == 0) {
        s_target = g_barflag + 1;
        s_flag = 0;
    }
    __syncthreads();

    // ---- dtype detect (fixed 32KB window; same answer in every block) ----
    {
        const uint32_t* ew = (const uint32_t*)ei_raw;
        int nz = 0;
        #pragma unroll
        for (int i = 0; i < 16; i++)
            nz |= (ew[2 * (tid + i * 256) + 1] != 0u);
        if (nz) s_flag = 1;
    }
    __syncthreads();
    int is64 = s_flag ? 0 : 1;

    // ================= PHASE 0: clear + decode/noise + GEMM =================

    // hash table clear (grid-strided int4)
    for (int i = bid * NTHR + tid; i < HCAP4; i += STRIDE) {
        ((int4*)g_keys)[i]   = make_int4(-1, -1, -1, -1);
        ((float4*)g_sums)[i] = make_float4(0.f, 0.f, 0.f, 0.f);
        ((int4*)g_cnts)[i]   = make_int4(0, 0, 0, 0);
    }

    // edge decode + clamp + threefry noise (grid-strided, coalesced)
    for (int e = bid * NTHR + tid; e < N_EDGES; e += STRIDE) {
        int c, r;
        if (is64) {
            const long long* p = (const long long*)ei_raw;
            c = (int)p[e];
            r = (int)p[N_EDGES + e];
        } else {
            const int* p = (const int*)ei_raw;
            c = p[e];
            r = p[N_EDGES + e];
        }
        c = min(max(c, 0), N_NODES - 1);
        r = min(max(r, 0), N_NODES - 1);
        g_ci[e] = make_int2(c, r);

        uint32_t o0, o1;
        threefry2x32(0u, 42u, 0u, (uint32_t)e, o0, o1);
        g_noise[e] = noise_from_bits(o0 ^ o1);
    }

    // node GEMM halves: A = embed @ W1[0:128], B = embed @ W1[128:256]
    for (int tile = bid; tile < GEMM_TILES; tile += NBLK) {
        int half = tile >= GEMM_HALF_TILES;
        int nb   = tile - half * GEMM_HALF_TILES;
        int n0   = nb * 32;
        int hq   = tid & 15;
        int gp   = tid >> 4;

        __syncthreads();
        const float4* emb4 = (const float4*)embed;
        size_t ebase = (size_t)n0 * (D_EMB / 4);
        float4* es4 = (float4*)es;
        #pragma unroll
        for (int i = 0; i < 4; i++) {
            size_t gidx = ebase + tid + i * 256;
            if (gidx < (size_t)N_NODES * (D_EMB / 4))
                es4[tid + i * 256] = emb4[gidx];
        }
        __syncthreads();

        const float4* W14 = (const float4*)(W1 + (size_t)half * D_EMB * HID);
        float4 a0 = make_float4(0.f, 0.f, 0.f, 0.f);
        float4 a1 = make_float4(0.f, 0.f, 0.f, 0.f);
        const float* er0 = es + (gp * 2)     * D_EMB;
        const float* er1 = es + (gp * 2 + 1) * D_EMB;
        #pragma unroll 8
        for (int d = 0; d < D_EMB; d++) {
            float4 w  = __ldg(&W14[d * 16 + hq]);
            float  e0 = er0[d];
            float  e1 = er1[d];
            a0.x = fmaf(e0, w.x, a0.x); a0.y = fmaf(e0, w.y, a0.y);
            a0.z = fmaf(e0, w.z, a0.z); a0.w = fmaf(e0, w.w, a0.w);
            a1.x = fmaf(e1, w.x, a1.x); a1.y = fmaf(e1, w.y, a1.y);
            a1.z = fmaf(e1, w.z, a1.z); a1.w = fmaf(e1, w.w, a1.w);
        }
        float4* dst = half ? (float4*)g_B : (float4*)g_A;
        int n = n0 + gp * 2;
        if (n < N_NODES)     dst[n * 16 + hq]       = a0;
        if (n + 1 < N_NODES) dst[(n + 1) * 16 + hq] = a1;
    }

    // ======================= GRID BARRIER (epoch) =======================
    __threadfence();          // publish phase-0 writes
    __syncthreads();
    if (tid == 0) {
        unsigned a = atomicAdd(&g_barcnt, 1);
        if (a == NBLK - 1) {
            g_barcnt = 0;
            __threadfence();
            g_barflag = s_target;
        } else {
            while (g_barflag != s_target) __nanosleep(64);
        }
        __threadfence();      // acquire
    }
    __syncthreads();

    // ============ PHASE 1: interleaved zero stores + edge work ============
    int warp = tid >> 5;
    int lane = tid & 31;
    int grp  = lane >> 3;
    int l8   = lane & 7;
    int gidx = bid * 32 + warp * 4 + grp;   // this 8-lane group's base edge

    const float4* b14 = (const float4*)b1;
    const float4* w24 = (const float4*)W2;
    float4 b1a = __ldg(&b14[l8 * 2]);
    float4 b1b = __ldg(&b14[l8 * 2 + 1]);
    float4 w2a = __ldg(&w24[l8 * 2]);
    float4 w2b = __ldg(&w24[l8 * 2 + 1]);
    float  bias2 = __ldg(&b2[0]);

    const float4* A4 = (const float4*)g_A;
    const float4* B4 = (const float4*)g_B;
    const float4  z4 = make_float4(0.f, 0.f, 0.f, 0.f);

    size_t zidx = (size_t)bid * NTHR + tid;
    int ec = 0;
    for (int t = 0; t < ZITER; t++) {
        if (zidx < OUT_F4) __stcs(&out[zidx], z4);
        zidx += STRIDE;

        if ((t & 3) == 0) {
            int e  = gidx + ec * NGRP;
            ec++;
            int ev = (e < N_EDGES);
            int ec2 = ev ? e : (N_EDGES - 1);   // clamp: keep lanes convergent

            int2 cr = g_ci[ec2];

            float4 av0 = A4[cr.x * 16 + l8 * 2];
            float4 av1 = A4[cr.x * 16 + l8 * 2 + 1];
            float4 bv0 = B4[cr.y * 16 + l8 * 2];
            float4 bv1 = B4[cr.y * 16 + l8 * 2 + 1];

            float s;
            s  = fmaxf(av0.x + bv0.x + b1a.x, 0.f) * w2a.x;
            s += fmaxf(av0.y + bv0.y + b1a.y, 0.f) * w2a.y;
            s += fmaxf(av0.z + bv0.z + b1a.z, 0.f) * w2a.z;
            s += fmaxf(av0.w + bv0.w + b1a.w, 0.f) * w2a.w;
            s += fmaxf(av1.x + bv1.x + b1b.x, 0.f) * w2b.x;
            s += fmaxf(av1.y + bv1.y + b1b.y, 0.f) * w2b.y;
            s += fmaxf(av1.z + bv1.z + b1b.z, 0.f) * w2b.z;
            s += fmaxf(av1.w + bv1.w + b1b.w, 0.f) * w2b.w;

            s += __shfl_xor_sync(0xffffffffu, s, 1);
            s += __shfl_xor_sync(0xffffffffu, s, 2);
            s += __shfl_xor_sync(0xffffffffu, s, 4);

            if (l8 == 0 && ev) {
                float x = g_noise[ec2] + s + bias2;
                float v = 1.0f / (1.0f + expf(-x));   // sigmoid

                uint32_t h = probe_slot(cr.x * N_NODES + cr.y);
                atomicAdd(&g_sums[h], v);
                atomicAdd(&g_cnts[h], 1);
                g_slot[ec2] = (int)h;
            }
        }
    }
}

// ---------------------------------------------------------------------------
// K_sym: per edge, out[c,r] = cnt * 0.5 * (S + S_transpose) (idempotent).
// ---------------------------------------------------------------------------
__global__ void k_sym(float* __restrict__ out) {
    int e = blockIdx.x * blockDim.x + threadIdx.x;
    if (e >= N_EDGES) return;
    int2 cr  = __ldg(&g_ci[e]);
    int slot = __ldg(&g_slot[e]);
    float S  = g_sums[slot];
    int  cnt = g_cnts[slot];

    int tkey = cr.y * N_NODES + cr.x;
    float ST = 0.0f;
    uint32_t h = cell_hash(tkey);
    while (true) {
        int k = g_keys[h];
        if (k == tkey) { ST = g_sums[h]; break; }
        if (k == -1) break;
        h = (h + 1) & HMASK;
    }
    __stcs(&out[(size_t)cr.x * N_NODES + cr.y], (float)cnt * 0.5f * (S + ST));
}

// ---------------------------------------------------------------------------
extern "C" void kernel_launch(void* const* d_in, const int* in_sizes, int n_in,
                              void* d_out, int out_size) {
    const float* embed = (const float*)d_in[0];
    const void*  ei    = d_in[1];
    const float* W1    = (const float*)d_in[2];
    const float* b1    = (const float*)d_in[3];
    const float* W2    = (const float*)d_in[4];
    const float* b2    = (const float*)d_in[5];
    float*       out   = (float*)d_out;

    // persistent: prep -> grid barrier -> interleaved zero + edge inserts
    k_main<<<NBLK, NTHR>>>(embed, W1, ei, b1, W2, b2, (float4*)out);

    // symmetrize + multiplicity -> idempotent streaming stores
    k_sym<<<(N_EDGES + 255) / 256, 256>>>(out);
}

// round 12
// speedup vs baseline: 1.1850x; 1.1850x over previous
#include <cuda_runtime.h>
#include <stdint.h>

// ---------------------------------------------------------------------------
// PGExplainer forward: masked_adj = adj * 0.5*(mask + mask^T)
// out[c,r] = cnt(c,r) * 0.5 * (S(c,r) + S(r,c)),  S = sum of sampled values
// Single-kernel ticket pipeline:
//   tickets [0, 3126):        prep  (GEMM tiles | decode+noise+table clear)
//   tickets [3126, 23126):    main  (1250-float4 zero slab + 32 edges, R7 body)
//   tickets [23126, 25626):   sym   (probe transpose, idempotent out stores)
// Roles gated by done-counters; ticket order == scheduling order => no deadlock.
// ---------------------------------------------------------------------------

#define N_NODES 10000
#define N_EDGES 640000
#define D_EMB   128
#define HID     64

#define OUT_ELEMS ((size_t)N_NODES * N_NODES)   // 1e8 floats = 400 MB
#define OUT_F4    (OUT_ELEMS / 4)               // 25,000,000 float4

#define HCAP  (1 << 21)
#define HMASK (HCAP - 1)
#define HCAP4 (HCAP / 4)

#define GEMM_HALF_TILES 313
#define GEMM_TILES      (2 * GEMM_HALF_TILES)    // 626
#define DEC_TICKETS     2500                     // 256 edges each
#define PREP_TICKETS    (GEMM_TILES + DEC_TICKETS)          // 3126
#define MAIN_TICKETS    20000                    // 1250 f4 zero + 32 edges each
#define SYM_TICKETS     2500                     // 256 edges each
#define TOTAL_TICKETS   (PREP_TICKETS + MAIN_TICKETS + SYM_TICKETS)  // 25626
#define ZPB4            1250                     // 20000*1250 = 25M exact

// Scratch (device globals).
__device__ float g_A[N_NODES * HID];
__device__ float g_B[N_NODES * HID];
__device__ float g_noise[N_EDGES];
__device__ int2  g_ci[N_EDGES];
__device__ int   g_slot[N_EDGES];
__device__ int   g_keys[HCAP];          // -1 = empty
__device__ float g_sums[HCAP];
__device__ int   g_cnts[HCAP];
// Pipeline state (all reset to 0 by the final sym block every call).
__device__ unsigned g_ticket;
__device__ unsigned g_prep_done;
__device__ unsigned g_main_done;
__device__ unsigned g_sym_done;

__device__ __forceinline__ uint32_t cell_hash(int key) {
    return ((uint32_t)key * 0x9E3779B1u) >> (32 - 21);
}

__device__ __forceinline__ uint32_t probe_slot(int key) {
    uint32_t h = cell_hash(key);
    while (true) {
        int k = g_keys[h];
        if (k == key) break;
        if (k == -1) {
            int old = atomicCAS(&g_keys[h], -1, key);
            if (old == -1 || old == key) break;
        }
        h = (h + 1) & HMASK;
    }
    return h;
}

// ---------------------------------------------------------------------------
// threefry2x32 (JAX schedule), key = (0, 42); partitionable stream.
// ---------------------------------------------------------------------------
__device__ __forceinline__ uint32_t rotl32(uint32_t x, int d) {
    return (x << d) | (x >> (32 - d));
}

__device__ __forceinline__ void threefry2x32(uint32_t k0, uint32_t k1,
                                             uint32_t x0, uint32_t x1,
                                             uint32_t& o0, uint32_t& o1) {
    uint32_t ks0 = k0, ks1 = k1, ks2 = k0 ^ k1 ^ 0x1BD11BDAu;
#define TF_R4(a, b, c, d)                            \
    x0 += x1; x1 = rotl32(x1, a); x1 ^= x0;          \
    x0 += x1; x1 = rotl32(x1, b); x1 ^= x0;          \
    x0 += x1; x1 = rotl32(x1, c); x1 ^= x0;          \
    x0 += x1; x1 = rotl32(x1, d); x1 ^= x0;
    x0 += ks0; x1 += ks1;
    TF_R4(13, 15, 26, 6);  x0 += ks1; x1 += ks2 + 1u;
    TF_R4(17, 29, 16, 24); x0 += ks2; x1 += ks0 + 2u;
    TF_R4(13, 15, 26, 6);  x0 += ks0; x1 += ks1 + 3u;
    TF_R4(17, 29, 16, 24); x0 += ks1; x1 += ks2 + 4u;
    TF_R4(13, 15, 26, 6);  x0 += ks2; x1 += ks0 + 5u;
#undef TF_R4
    o0 = x0; o1 = x1;
}

__device__ __forceinline__ float noise_from_bits(uint32_t bits) {
    float u = __uint_as_float((bits >> 9) | 0x3f800000u) - 1.0f;   // [0,1)
    return logf(u) - log1pf(-u);   // u==0 -> -inf -> sigmoid -> 0
}

__device__ __forceinline__ void spin_until(volatile unsigned* p, unsigned tgt) {
    while (*p != tgt) __nanosleep(64);
}

// ---------------------------------------------------------------------------
// K_all: the whole pipeline in one launch.
// ---------------------------------------------------------------------------
__global__ void __launch_bounds__(256) k_all(const float* __restrict__ embed,
                                             const float* __restrict__ W1,
                                             const void* __restrict__ ei_raw,
                                             const float* __restrict__ b1,
                                             const float* __restrict__ W2,
                                             const float* __restrict__ b2,
                                             float4* __restrict__ out) {
    __shared__ float    es[32 * D_EMB];      // 16 KB (GEMM staging)
    __shared__ unsigned s_ticket;
    __shared__ int      s_flag;

    int tid = threadIdx.x;

    if (tid == 0) s_ticket = atomicAdd(&g_ticket, 1u);
    __syncthreads();
    unsigned ticket = s_ticket;

    // ======================= PREP ROLE =======================
    if (ticket < PREP_TICKETS) {
        if (ticket < GEMM_TILES) {
            // ---- node GEMM halves ----
            int half = ticket >= GEMM_HALF_TILES;
            int nb   = (int)ticket - half * GEMM_HALF_TILES;
            int n0   = nb * 32;
            int hq   = tid & 15;
            int gp   = tid >> 4;

            const float4* emb4 = (const float4*)embed;
            size_t ebase = (size_t)n0 * (D_EMB / 4);
            float4* es4 = (float4*)es;
            #pragma unroll
            for (int i = 0; i < 4; i++) {
                size_t gidx = ebase + tid + i * 256;
                if (gidx < (size_t)N_NODES * (D_EMB / 4))
                    es4[tid + i * 256] = emb4[gidx];
            }
            __syncthreads();

            const float4* W14 = (const float4*)(W1 + (size_t)half * D_EMB * HID);
            float4 a0 = make_float4(0.f, 0.f, 0.f, 0.f);
            float4 a1 = make_float4(0.f, 0.f, 0.f, 0.f);
            const float* er0 = es + (gp * 2)     * D_EMB;
            const float* er1 = es + (gp * 2 + 1) * D_EMB;
            #pragma unroll 8
            for (int d = 0; d < D_EMB; d++) {
                float4 w  = __ldg(&W14[d * 16 + hq]);
                float  e0 = er0[d];
                float  e1 = er1[d];
                a0.x = fmaf(e0, w.x, a0.x); a0.y = fmaf(e0, w.y, a0.y);
                a0.z = fmaf(e0, w.z, a0.z); a0.w = fmaf(e0, w.w, a0.w);
                a1.x = fmaf(e1, w.x, a1.x); a1.y = fmaf(e1, w.y, a1.y);
                a1.z = fmaf(e1, w.z, a1.z); a1.w = fmaf(e1, w.w, a1.w);
            }
            float4* dst = half ? (float4*)g_B : (float4*)g_A;
            int n = n0 + gp * 2;
            if (n < N_NODES)     dst[n * 16 + hq]       = a0;
            if (n + 1 < N_NODES) dst[(n + 1) * 16 + hq] = a1;
        } else {
            // ---- decode + noise + table clear ----
            int dt = (int)ticket - GEMM_TILES;      // 0..2499
            int e  = dt * 256 + tid;

            // dtype detect on a fixed 32KB window (same answer per block)
            if (tid == 0) s_flag = 0;
            __syncthreads();
            {
                const uint32_t* ew = (const uint32_t*)ei_raw;
                int nz = 0;
                #pragma unroll
                for (int i = 0; i < 16; i++)
                    nz |= (ew[2 * (tid + i * 256) + 1] != 0u);
                if (nz) s_flag = 1;
            }
            __syncthreads();
            int is64 = s_flag ? 0 : 1;

            // striped table clear: 2500 blocks x 256 threads covers HCAP4
            for (int i = dt * 256 + tid; i < HCAP4; i += DEC_TICKETS * 256) {
                ((int4*)g_keys)[i]   = make_int4(-1, -1, -1, -1);
                ((float4*)g_sums)[i] = make_float4(0.f, 0.f, 0.f, 0.f);
                ((int4*)g_cnts)[i]   = make_int4(0, 0, 0, 0);
            }

            if (e < N_EDGES) {
                int c, r;
                if (is64) {
                    const long long* p = (const long long*)ei_raw;
                    c = (int)p[e];
                    r = (int)p[N_EDGES + e];
                } else {
                    const int* p = (const int*)ei_raw;
                    c = p[e];
                    r = p[N_EDGES + e];
                }
                c = min(max(c, 0), N_NODES - 1);
                r = min(max(r, 0), N_NODES - 1);
                g_ci[e] = make_int2(c, r);

                uint32_t o0, o1;
                threefry2x32(0u, 42u, 0u, (uint32_t)e, o0, o1);
                g_noise[e] = noise_from_bits(o0 ^ o1);
            }
        }
        __threadfence();
        __syncthreads();
        if (tid == 0) atomicAdd(&g_prep_done, 1u);
        return;
    }

    // ======================= MAIN ROLE (R7 fused body) =======================
    if (ticket < PREP_TICKETS + MAIN_TICKETS) {
        int m = (int)(ticket - PREP_TICKETS);    // 0..19999

        // wait for prep (prep tickets all precede main tickets in schedule)
        if (tid == 0) spin_until(&g_prep_done, PREP_TICKETS);
        __syncthreads();
        __threadfence();

        // ---- zero slab (exact coverage, streaming stores) ----
        const float4 z4 = make_float4(0.f, 0.f, 0.f, 0.f);
        size_t zbase = (size_t)m * ZPB4;
        #pragma unroll
        for (int i = 0; i < 4; i++)
            __stcs(&out[zbase + tid + i * 256], z4);
        if (tid < ZPB4 - 1024)
            __stcs(&out[zbase + tid + 1024], z4);

        // ---- 32 edges: one 8-lane group per edge ----
        int warp = tid >> 5;
        int lane = tid & 31;
        int grp  = lane >> 3;
        int l8   = lane & 7;
        int e    = m * 32 + warp * 4 + grp;

        int2 cr = g_ci[e];

        const float4* b14 = (const float4*)b1;
        const float4* w24 = (const float4*)W2;
        float4 b1a = __ldg(&b14[l8 * 2]);
        float4 b1b = __ldg(&b14[l8 * 2 + 1]);
        float4 w2a = __ldg(&w24[l8 * 2]);
        float4 w2b = __ldg(&w24[l8 * 2 + 1]);

        const float4* A4 = (const float4*)g_A;
        const float4* B4 = (const float4*)g_B;
        float4 av0 = A4[cr.x * 16 + l8 * 2];
        float4 av1 = A4[cr.x * 16 + l8 * 2 + 1];
        float4 bv0 = B4[cr.y * 16 + l8 * 2];
        float4 bv1 = B4[cr.y * 16 + l8 * 2 + 1];

        float s;
        s  = fmaxf(av0.x + bv0.x + b1a.x, 0.f) * w2a.x;
        s += fmaxf(av0.y + bv0.y + b1a.y, 0.f) * w2a.y;
        s += fmaxf(av0.z + bv0.z + b1a.z, 0.f) * w2a.z;
        s += fmaxf(av0.w + bv0.w + b1a.w, 0.f) * w2a.w;
        s += fmaxf(av1.x + bv1.x + b1b.x, 0.f) * w2b.x;
        s += fmaxf(av1.y + bv1.y + b1b.y, 0.f) * w2b.y;
        s += fmaxf(av1.z + bv1.z + b1b.z, 0.f) * w2b.z;
        s += fmaxf(av1.w + bv1.w + b1b.w, 0.f) * w2b.w;

        s += __shfl_xor_sync(0xffffffffu, s, 1);
        s += __shfl_xor_sync(0xffffffffu, s, 2);
        s += __shfl_xor_sync(0xffffffffu, s, 4);

        if (l8 == 0) {
            float x = g_noise[e] + s + __ldg(&b2[0]);
            float v = 1.0f / (1.0f + expf(-x));   // sigmoid

            uint32_t h = probe_slot(cr.x * N_NODES + cr.y);
            atomicAdd(&g_sums[h], v);
            atomicAdd(&g_cnts[h], 1);
            g_slot[e] = (int)h;
        }

        __threadfence();
        __syncthreads();
        if (tid == 0) atomicAdd(&g_main_done, 1u);
        return;
    }

    // ======================= SYM ROLE =======================
    {
        int st = (int)(ticket - PREP_TICKETS - MAIN_TICKETS);  // 0..2499

        if (tid == 0) spin_until(&g_main_done, MAIN_TICKETS);
        __syncthreads();
        __threadfence();

        int e = st * 256 + tid;
        if (e < N_EDGES) {
            int2 cr  = __ldg(&g_ci[e]);
            int slot = __ldg(&g_slot[e]);
            float S  = g_sums[slot];
            int  cnt = g_cnts[slot];

            int tkey = cr.y * N_NODES + cr.x;
            float ST = 0.0f;
            uint32_t h = cell_hash(tkey);
            while (true) {
                int k = g_keys[h];
                if (k == tkey) { ST = g_sums[h]; break; }
                if (k == -1) break;
                h = (h + 1) & HMASK;
            }
            __stcs(&((float*)out)[(size_t)cr.x * N_NODES + cr.y],
                   (float)cnt * 0.5f * (S + ST));
        }

        // last sym block resets pipeline state for the next graph replay
        __threadfence();
        __syncthreads();
        if (tid == 0) {
            unsigned d = atomicAdd(&g_sym_done, 1u);
            if (d == SYM_TICKETS - 1) {
                g_ticket    = 0;
                g_prep_done = 0;
                g_main_done = 0;
                g_sym_done  = 0;
                __threadfence();
            }
        }
    }
}

// ---------------------------------------------------------------------------
extern "C" void kernel_launch(void* const* d_in, const int* in_sizes, int n_in,
                              void* d_out, int out_size) {
    const float* embed = (const float*)d_in[0];
    const void*  ei    = d_in[1];
    const float* W1    = (const float*)d_in[2];
    const float* b1    = (const float*)d_in[3];
    const float* W2    = (const float*)d_in[4];
    const float* b2    = (const float*)d_in[5];
    float*       out   = (float*)d_out;

    k_all<<<TOTAL_TICKETS, 256>>>(embed, W1, ei, b1, W2, b2, (float4*)out);
}